// round 15
// baseline (speedup 1.0000x reference)
#include <cuda_runtime.h>
#include <cuda_fp16.h>
#include <cstdint>

// ---------------------------------------------------------------------------
// Problem constants
// ---------------------------------------------------------------------------
#define U_NODES 200000
#define F_DIM   256
#define E_DIM   128
#define B_ROWS  20000
#define K_SAMP  33
#define BN_EPS  1e-5f

#define TM      128
#define TN      64                        // N half per CTA
#define KC      64                        // K chunk (fp16 elems)
#define NCH     (F_DIM / KC)              // 4
#define NTILES  ((U_NODES + TM - 1) / TM) // 1563

// SMEM layout (bytes, dynamic)
#define OFF_BIAS   0                          // 256 B (64 floats)
#define OFF_W      512                        // 32 KB (fp16 W half, whole K)
#define OFF_A      (OFF_W + 32768)            // 2 stages x 16KB (fp16 A)
#define OFF_RED    (OFF_A + 32768)            // 2 KB stats reduction
#define SMEM_TOTAL (OFF_RED + 2048)           // 68096 -> 3 CTAs/SM

// ---------------------------------------------------------------------------
// Device scratch
// ---------------------------------------------------------------------------
__device__ __half g_h[(size_t)U_NODES * E_DIM];      // h in fp16 (51.2 MB)
__device__ float g_part[NTILES * 2 * E_DIM];
__device__ __align__(16) float g_ab[2 * E_DIM];
// W images: per N-half: [K=256 rows][64 cols] fp16 (128B rows),
// 16B-col XOR-swizzle by (k&7)
__device__ __align__(16) __half g_wh[2][F_DIM * TN];

// ---------------------------------------------------------------------------
// Helpers
// ---------------------------------------------------------------------------
__device__ __forceinline__ uint32_t smem_u32(const void* p) {
    uint32_t a;
    asm("{ .reg .u64 t; cvta.to.shared.u64 t, %1; cvt.u32.u64 %0, t; }"
        : "=r"(a) : "l"(p));
    return a;
}
__device__ __forceinline__ void sts128(uint32_t addr, uint32_t a, uint32_t b,
                                       uint32_t c, uint32_t d) {
    asm volatile("st.shared.v4.b32 [%0], {%1, %2, %3, %4};"
                 :: "r"(addr), "r"(a), "r"(b), "r"(c), "r"(d) : "memory");
}
__device__ __forceinline__ void cp16(uint32_t s, const void* g) {
    asm volatile("cp.async.cg.shared.global [%0], [%1], 16;"
                 :: "r"(s), "l"(g) : "memory");
}
__device__ __forceinline__ void cp_commit() {
    asm volatile("cp.async.commit_group;" ::: "memory");
}
__device__ __forceinline__ void cp_wait0() {
    asm volatile("cp.async.wait_group 0;" ::: "memory");
}
__device__ __forceinline__ void ldmx4(uint32_t addr, uint32_t* r) {
    asm volatile("ldmatrix.sync.aligned.m8n8.x4.shared.b16 {%0,%1,%2,%3}, [%4];"
                 : "=r"(r[0]), "=r"(r[1]), "=r"(r[2]), "=r"(r[3]) : "r"(addr));
}
__device__ __forceinline__ void ldmx4t(uint32_t addr, uint32_t* r) {
    asm volatile("ldmatrix.sync.aligned.m8n8.x4.trans.shared.b16 {%0,%1,%2,%3}, [%4];"
                 : "=r"(r[0]), "=r"(r[1]), "=r"(r[2]), "=r"(r[3]) : "r"(addr));
}
__device__ __forceinline__ void mma_f16(float* d, const uint32_t* a,
                                        uint32_t b0, uint32_t b1) {
    asm volatile(
        "mma.sync.aligned.m16n8k16.row.col.f32.f16.f16.f32 "
        "{%0,%1,%2,%3}, {%4,%5,%6,%7}, {%8,%9}, {%0,%1,%2,%3};"
        : "+f"(d[0]), "+f"(d[1]), "+f"(d[2]), "+f"(d[3])
        : "r"(a[0]), "r"(a[1]), "r"(a[2]), "r"(a[3]), "r"(b0), "r"(b1));
}
__device__ __forceinline__ uint32_t pack_f16x2(float lo, float hi) {
    uint32_t r;
    asm("cvt.rn.f16x2.f32 %0, %1, %2;" : "=r"(r) : "f"(hi), "f"(lo));
    return r;
}

// ---------------------------------------------------------------------------
// Kernel 0: W [256,128] fp32 -> fp16 half-images, [K][64] 128B rows, swizzled.
// byte offset within half = k*128 + ((nn*2) ^ ((k&7)<<4)), nn = n & 63
// ---------------------------------------------------------------------------
__global__ void prep_w_kernel(const float* __restrict__ W) {
    int idx = blockIdx.x * 256 + threadIdx.x;    // 0..32767
    int k = idx >> 7;
    int n = idx & 127;
    int half = n >> 6;
    int nn = n & 63;
    uint32_t off = (uint32_t)k * 128 + (((uint32_t)nn * 2) ^ ((k & 7) << 4));
    g_wh[half][off >> 1] = __float2half_rn(W[idx]);
}

// ---------------------------------------------------------------------------
// Kernel 1: h = A @ W + b (mma.sync fp16), split-N: each CTA does 128x64.
// grid (2, NTILES): blockIdx.x = N half (adjacent scheduling -> A L2 reuse),
// blockIdx.y = M tile. 256 threads = 8 warps (4x2 over 128x64), 3 CTAs/SM.
// Producer/MMA/epilogue logic identical to the proven R9 kernel, N halved.
// ---------------------------------------------------------------------------
__global__ void __launch_bounds__(256, 3)
gemm_mma_kernel(const float* __restrict__ A, const float* __restrict__ bias)
{
    extern __shared__ char smem[];
    const uint32_t sm = smem_u32(smem);
    const int tid  = threadIdx.x;
    const int wid  = tid >> 5;
    const int lane = tid & 31;
    const int half = blockIdx.x;          // 0,1 -> N half
    const int row0 = blockIdx.y * TM;
    const int col0 = half * TN;
    const int warp_m = wid >> 1;          // 0..3 -> 32-row band
    const int warp_n = wid & 1;           // 0..1 -> 32-col band (within half)

    float* sbias = (float*)(smem + OFF_BIAS);
    if (tid < TN) sbias[tid] = bias[col0 + tid];

    // ---- load W half (32KB fp16) once via cp.async ----
    {
        const char* src = (const char*)g_wh[half];
        const uint32_t dst = sm + OFF_W;
#pragma unroll
        for (int j = 0; j < 8; j++) {
            const int u = tid + j * 256;          // 16B units, 0..2047
            cp16(dst + u * 16, src + (size_t)u * 16);
        }
        cp_commit();
    }

    // ---- producer mapping: thread -> (row, 32-float half-chunk) ----
    const int pr = tid >> 1;             // 0..127
    const int ph = tid & 1;              // half of the 64-float chunk
    const bool pvalid = (row0 + pr) < U_NODES;
    const float* aptr = A + (size_t)(row0 + pr) * F_DIM + ph * 32;
    uint32_t a_sts[4];
#pragma unroll
    for (int i = 0; i < 4; i++)
        a_sts[i] = (uint32_t)pr * 128 +
                   (((uint32_t)(ph * 64 + i * 16)) ^ ((pr & 7) << 4));

    // ---- MMA-side addressing ----
    uint32_t aoff[2], axor[2];
#pragma unroll
    for (int am = 0; am < 2; am++) {
        int r = warp_m * 32 + am * 16 + (lane & 15);
        aoff[am] = (uint32_t)r * 128;
        axor[am] = (uint32_t)(r & 7) << 4;
    }
    const uint32_t acolb = (uint32_t)(lane >> 4) * 16;
    const int bk = lane & 15;
    uint32_t bcol[2];
#pragma unroll
    for (int nb = 0; nb < 2; nb++)
        bcol[nb] = (((uint32_t)(warp_n * 32 + nb * 16 + (lane >> 4) * 8) * 2)
                    ^ ((bk & 7) << 4));
    const uint32_t brow = (uint32_t)bk * 128;    // 128B rows in W half-image

    float acc[2][4][4];
#pragma unroll
    for (int am = 0; am < 2; am++)
#pragma unroll
        for (int na = 0; na < 4; na++)
#pragma unroll
            for (int q = 0; q < 4; q++) acc[am][na][q] = 0.f;

    cp_wait0();
    __syncthreads();

    for (int c = 0; c < NCH; c++) {
        const int stage = c & 1;

        // producer: LDG 32 floats -> fp16x2 -> STS
        {
            uint32_t hw[16];
            if (pvalid) {
                const float4* p = (const float4*)(aptr + c * KC);
#pragma unroll
                for (int i = 0; i < 8; i++) {
                    float4 v = p[i];
                    hw[2 * i]     = pack_f16x2(v.x, v.y);
                    hw[2 * i + 1] = pack_f16x2(v.z, v.w);
                }
            } else {
#pragma unroll
                for (int i = 0; i < 16; i++) hw[i] = 0u;
            }
            const uint32_t ab = sm + OFF_A + stage * 16384;
#pragma unroll
            for (int i = 0; i < 4; i++)
                sts128(ab + a_sts[i], hw[4 * i], hw[4 * i + 1],
                       hw[4 * i + 2], hw[4 * i + 3]);
        }
        __syncthreads();

        const uint32_t Ahb = sm + OFF_A + stage * 16384;
        const uint32_t Whb = sm + OFF_W + (uint32_t)c * 8192;
#pragma unroll
        for (int ks = 0; ks < 4; ks++) {
            uint32_t ah[2][4];
#pragma unroll
            for (int am = 0; am < 2; am++)
                ldmx4(Ahb + aoff[am] + ((acolb + ks * 32) ^ axor[am]), ah[am]);
#pragma unroll
            for (int nb = 0; nb < 2; nb++) {
                uint32_t bh[4];
                ldmx4t(Whb + (uint32_t)ks * 2048 + brow + bcol[nb], bh);
#pragma unroll
                for (int am = 0; am < 2; am++) {
                    mma_f16(acc[am][nb * 2],     ah[am], bh[0], bh[1]);
                    mma_f16(acc[am][nb * 2 + 1], ah[am], bh[2], bh[3]);
                }
            }
        }
    }

    // ---- epilogue: direct fp16 STG + register/shuffle column stats ----
    const int colb = warp_n * 32 + (lane & 3) * 2;   // col within half
    float2 b2[4];
#pragma unroll
    for (int na = 0; na < 4; na++)
        b2[na] = *(const float2*)&sbias[colb + na * 8];

    float s0[4], s1[4], q0[4], q1[4];
#pragma unroll
    for (int na = 0; na < 4; na++) { s0[na] = s1[na] = q0[na] = q1[na] = 0.f; }

#pragma unroll
    for (int am = 0; am < 2; am++) {
        const int rA = warp_m * 32 + am * 16 + (lane >> 2);
#pragma unroll
        for (int hh = 0; hh < 2; hh++) {
            const int r = rA + hh * 8;
            const bool v = (row0 + r) < U_NODES;
            __half* dst = g_h + (size_t)(row0 + r) * E_DIM + col0 + colb;
#pragma unroll
            for (int na = 0; na < 4; na++) {
                float x0 = acc[am][na][hh * 2]     + b2[na].x;
                float x1 = acc[am][na][hh * 2 + 1] + b2[na].y;
                if (v) {
                    *(uint32_t*)(dst + na * 8) = pack_f16x2(x0, x1);
                    s0[na] += x0; s1[na] += x1;
                    q0[na] += x0 * x0; q1[na] += x1 * x1;
                }
            }
        }
    }
#pragma unroll
    for (int m = 4; m <= 16; m <<= 1) {
#pragma unroll
        for (int na = 0; na < 4; na++) {
            s0[na] += __shfl_xor_sync(0xFFFFFFFFu, s0[na], m);
            s1[na] += __shfl_xor_sync(0xFFFFFFFFu, s1[na], m);
            q0[na] += __shfl_xor_sync(0xFFFFFFFFu, q0[na], m);
            q1[na] += __shfl_xor_sync(0xFFFFFFFFu, q1[na], m);
        }
    }
    __syncthreads();                       // MMA reads of A bufs done
    float* red_s = (float*)(smem + OFF_RED);          // [4 warp_m][64]
    float* red_q = red_s + 256;
    if (lane < 4) {
#pragma unroll
        for (int na = 0; na < 4; na++) {
            const int col = warp_n * 32 + na * 8 + lane * 2;
            red_s[warp_m * 64 + col]     = s0[na];
            red_s[warp_m * 64 + col + 1] = s1[na];
            red_q[warp_m * 64 + col]     = q0[na];
            red_q[warp_m * 64 + col + 1] = q1[na];
        }
    }
    __syncthreads();
    if (tid < TN) {
        float ts = red_s[tid] + red_s[64 + tid] +
                   red_s[128 + tid] + red_s[192 + tid];
        float tq = red_q[tid] + red_q[64 + tid] +
                   red_q[128 + tid] + red_q[192 + tid];
        g_part[blockIdx.y * 256 + col0 + tid]       = ts;
        g_part[blockIdx.y * 256 + 128 + col0 + tid] = tq;
    }
}

// ---------------------------------------------------------------------------
// Kernel 2: finalize BN stats (one block per embedding column)
// ---------------------------------------------------------------------------
__global__ void finalize_stats_kernel(const float* __restrict__ gamma,
                                      const float* __restrict__ beta)
{
    __shared__ float ss[256], sq[256];
    const int e = blockIdx.x;
    const int t = threadIdx.x;
    float s = 0.f, q = 0.f;
    for (int i = t; i < NTILES; i += 256) {
        s += g_part[i * 256 + e];
        q += g_part[i * 256 + 128 + e];
    }
    ss[t] = s; sq[t] = q;
    __syncthreads();
    for (int st = 128; st > 0; st >>= 1) {
        if (t < st) { ss[t] += ss[t + st]; sq[t] += sq[t + st]; }
        __syncthreads();
    }
    if (t == 0) {
        const float mu  = ss[0] * (1.0f / U_NODES);
        const float var = sq[0] * (1.0f / U_NODES) - mu * mu;
        const float a   = gamma[e] * rsqrtf(var + BN_EPS);
        g_ab[e]         = a;
        g_ab[E_DIM + e] = beta[e] - mu * a;
    }
}

// ---------------------------------------------------------------------------
// Kernel 3: out[b] = mean_k tanh(a * h[idx[b,k]] + c), h in fp16
// one warp per output row, uint2 (4 halves) per lane covers the 256B row
// ---------------------------------------------------------------------------
__global__ void __launch_bounds__(128)
gather_mean_kernel(const int* __restrict__ idx, float* __restrict__ out)
{
    __shared__ int sidx[4 * K_SAMP];
    const int b0 = blockIdx.x * 4;
    const int tid = threadIdx.x;
    const int w = tid >> 5;
    const int lane = tid & 31;
    for (int i = tid; i < 4 * K_SAMP; i += 128)
        sidx[i] = idx[b0 * K_SAMP + i];
    __syncthreads();

    const float4 a4 = *(const float4*)&g_ab[lane * 4];
    const float4 c4 = *(const float4*)&g_ab[E_DIM + lane * 4];
    float4 acc = make_float4(0.f, 0.f, 0.f, 0.f);
    const int* myidx = sidx + w * K_SAMP;
#pragma unroll 3
    for (int k = 0; k < K_SAMP; k++) {
        const uint2 u = __ldg((const uint2*)(g_h + (size_t)myidx[k] * E_DIM)
                              + lane);
        const float2 f0 = __half22float2(*(const half2*)&u.x);
        const float2 f1 = __half22float2(*(const half2*)&u.y);
        float t0, t1, t2, t3;
        asm("tanh.approx.f32 %0, %1;" : "=f"(t0) : "f"(fmaf(a4.x, f0.x, c4.x)));
        asm("tanh.approx.f32 %0, %1;" : "=f"(t1) : "f"(fmaf(a4.y, f0.y, c4.y)));
        asm("tanh.approx.f32 %0, %1;" : "=f"(t2) : "f"(fmaf(a4.z, f1.x, c4.z)));
        asm("tanh.approx.f32 %0, %1;" : "=f"(t3) : "f"(fmaf(a4.w, f1.y, c4.w)));
        acc.x += t0; acc.y += t1; acc.z += t2; acc.w += t3;
    }
    const float sc = 1.0f / K_SAMP;
    float4 o = make_float4(acc.x * sc, acc.y * sc, acc.z * sc, acc.w * sc);
    *(float4*)(out + (size_t)(b0 + w) * E_DIM + lane * 4) = o;
}

// ---------------------------------------------------------------------------
extern "C" void kernel_launch(void* const* d_in, const int* in_sizes, int n_in,
                              void* d_out, int out_size)
{
    const float* features = (const float*)d_in[0];
    const float* W        = (const float*)d_in[1];
    const float* bias     = (const float*)d_in[2];
    const float* gamma    = (const float*)d_in[3];
    const float* beta     = (const float*)d_in[4];
    const int*   sidx     = (const int*)d_in[5];
    float*       out      = (float*)d_out;

    cudaFuncSetAttribute(gemm_mma_kernel,
                         cudaFuncAttributeMaxDynamicSharedMemorySize, SMEM_TOTAL);

    prep_w_kernel<<<128, 256>>>(W);
    dim3 grid(2, NTILES);
    gemm_mma_kernel<<<grid, 256, SMEM_TOTAL>>>(features, bias);
    finalize_stats_kernel<<<128, 256>>>(gamma, beta);
    gather_mean_kernel<<<B_ROWS / 4, 128>>>(sidx, out);
}

// round 16
// speedup vs baseline: 1.6790x; 1.6790x over previous
#include <cuda_runtime.h>
#include <cuda_fp16.h>
#include <cstdint>

// ---------------------------------------------------------------------------
// Problem constants
// ---------------------------------------------------------------------------
#define U_NODES 200000
#define F_DIM   256
#define E_DIM   128
#define B_ROWS  20000
#define K_SAMP  33
#define BN_EPS  1e-5f

#define TM      128
#define KC      64                        // K chunk (fp16 elems)
#define NCH     (F_DIM / KC)              // 4
#define NTILES  ((U_NODES + TM - 1) / TM) // 1563

// SMEM layout (bytes, dynamic)
#define OFF_BIAS   0                          // 512 B
#define OFF_W      512                        // 64 KB (fp16 W, whole K)
#define OFF_A      (OFF_W + 65536)            // 2 stages x 16KB (fp16 A)
#define SMEM_TOTAL (OFF_A + 32768)            // 98816 -> 2 CTAs/SM

// ---------------------------------------------------------------------------
// Device scratch
// ---------------------------------------------------------------------------
__device__ __half g_h[(size_t)U_NODES * E_DIM];      // h in fp16 (51.2 MB)
__device__ float g_part[NTILES * 2 * E_DIM];
__device__ __align__(16) float g_ab[2 * E_DIM];
// W image: [K=256 rows][N=128] fp16 (256B rows), 16B-col XOR-swizzle by (k&7)
__device__ __align__(16) __half g_wh[F_DIM * E_DIM];

// ---------------------------------------------------------------------------
// Helpers
// ---------------------------------------------------------------------------
__device__ __forceinline__ uint32_t smem_u32(const void* p) {
    uint32_t a;
    asm("{ .reg .u64 t; cvta.to.shared.u64 t, %1; cvt.u32.u64 %0, t; }"
        : "=r"(a) : "l"(p));
    return a;
}
__device__ __forceinline__ void sts128(uint32_t addr, uint32_t a, uint32_t b,
                                       uint32_t c, uint32_t d) {
    asm volatile("st.shared.v4.b32 [%0], {%1, %2, %3, %4};"
                 :: "r"(addr), "r"(a), "r"(b), "r"(c), "r"(d) : "memory");
}
__device__ __forceinline__ void cp16(uint32_t s, const void* g) {
    asm volatile("cp.async.cg.shared.global [%0], [%1], 16;"
                 :: "r"(s), "l"(g) : "memory");
}
__device__ __forceinline__ void cp_commit() {
    asm volatile("cp.async.commit_group;" ::: "memory");
}
__device__ __forceinline__ void cp_wait0() {
    asm volatile("cp.async.wait_group 0;" ::: "memory");
}
__device__ __forceinline__ void ldmx4(uint32_t addr, uint32_t* r) {
    asm volatile("ldmatrix.sync.aligned.m8n8.x4.shared.b16 {%0,%1,%2,%3}, [%4];"
                 : "=r"(r[0]), "=r"(r[1]), "=r"(r[2]), "=r"(r[3]) : "r"(addr));
}
__device__ __forceinline__ void ldmx4t(uint32_t addr, uint32_t* r) {
    asm volatile("ldmatrix.sync.aligned.m8n8.x4.trans.shared.b16 {%0,%1,%2,%3}, [%4];"
                 : "=r"(r[0]), "=r"(r[1]), "=r"(r[2]), "=r"(r[3]) : "r"(addr));
}
__device__ __forceinline__ void mma_f16(float* d, const uint32_t* a,
                                        uint32_t b0, uint32_t b1) {
    asm volatile(
        "mma.sync.aligned.m16n8k16.row.col.f32.f16.f16.f32 "
        "{%0,%1,%2,%3}, {%4,%5,%6,%7}, {%8,%9}, {%0,%1,%2,%3};"
        : "+f"(d[0]), "+f"(d[1]), "+f"(d[2]), "+f"(d[3])
        : "r"(a[0]), "r"(a[1]), "r"(a[2]), "r"(a[3]), "r"(b0), "r"(b1));
}
__device__ __forceinline__ uint32_t pack_f16x2(float lo, float hi) {
    uint32_t r;
    asm("cvt.rn.f16x2.f32 %0, %1, %2;" : "=r"(r) : "f"(hi), "f"(lo));
    return r;
}

// ---------------------------------------------------------------------------
// Kernel 0: W [256,128] fp32 -> fp16, [K][N] row-major, swizzled.
// byte offset = k*256 + ((n*2) ^ ((k&7)<<4))
// ---------------------------------------------------------------------------
__global__ void prep_w_kernel(const float* __restrict__ W) {
    int idx = blockIdx.x * 256 + threadIdx.x;    // 0..32767
    int k = idx >> 7;
    int n = idx & 127;
    uint32_t off = (uint32_t)k * 256 + (((uint32_t)n * 2) ^ ((k & 7) << 4));
    g_wh[off >> 1] = __float2half_rn(W[idx]);
}

// ---------------------------------------------------------------------------
// Kernel 1: h = A @ W + b via mma.sync fp16, fused col stats, h stored fp16.
// 512 threads = 16 warps (4x4 grid of 32x32 tiles), 2 CTAs/SM.
// Grid-launched (HW CTA rotation overlaps serial phases across co-resident
// CTAs; measured better than persistence, prefetch, sync-free, and split-N).
// ---------------------------------------------------------------------------
__global__ void __launch_bounds__(512, 2)
gemm_mma_kernel(const float* __restrict__ A, const float* __restrict__ bias)
{
    extern __shared__ char smem[];
    const uint32_t sm = smem_u32(smem);
    const int tid  = threadIdx.x;
    const int wid  = tid >> 5;
    const int lane = tid & 31;
    const int row0 = blockIdx.x * TM;
    const int warp_m = wid >> 2;          // 0..3 -> 32-row band
    const int warp_n = wid & 3;           // 0..3 -> 32-col band

    float* sbias = (float*)(smem + OFF_BIAS);
    if (tid < 128) sbias[tid] = bias[tid];

    // ---- load full W (64KB fp16) once via cp.async ----
    {
        const char* src = (const char*)g_wh;
        const uint32_t dst = sm + OFF_W;
#pragma unroll
        for (int j = 0; j < 8; j++) {
            const int u = tid + j * 512;          // 16B units, 0..4095
            cp16(dst + u * 16, src + (size_t)u * 16);
        }
        cp_commit();
    }

    // ---- producer mapping: thread -> (row, 16-float quarter) ----
    const int pr = tid >> 2;             // 0..127
    const int pq = tid & 3;
    const bool pvalid = (row0 + pr) < U_NODES;
    const float* aptr = A + (size_t)(row0 + pr) * F_DIM + pq * 16;
    uint32_t a_sts[2];
#pragma unroll
    for (int i = 0; i < 2; i++)
        a_sts[i] = (uint32_t)pr * 128 +
                   (((uint32_t)(pq * 32 + i * 16)) ^ ((pr & 7) << 4));

    // ---- MMA-side addressing ----
    uint32_t aoff[2], axor[2];
#pragma unroll
    for (int am = 0; am < 2; am++) {
        int r = warp_m * 32 + am * 16 + (lane & 15);
        aoff[am] = (uint32_t)r * 128;
        axor[am] = (uint32_t)(r & 7) << 4;
    }
    const uint32_t acolb = (uint32_t)(lane >> 4) * 16;
    const int bk = lane & 15;
    uint32_t bcol[2];
#pragma unroll
    for (int nb = 0; nb < 2; nb++)
        bcol[nb] = (((uint32_t)(warp_n * 32 + nb * 16 + (lane >> 4) * 8) * 2)
                    ^ ((bk & 7) << 4));
    const uint32_t brow = (uint32_t)bk * 256;

    float acc[2][4][4];
#pragma unroll
    for (int am = 0; am < 2; am++)
#pragma unroll
        for (int na = 0; na < 4; na++)
#pragma unroll
            for (int q = 0; q < 4; q++) acc[am][na][q] = 0.f;

    cp_wait0();
    __syncthreads();

    for (int c = 0; c < NCH; c++) {
        const int stage = c & 1;

        // producer: LDG 16 floats -> fp16x2 -> STS
        {
            uint32_t hw[8];
            if (pvalid) {
                const float4* p = (const float4*)(aptr + c * KC);
#pragma unroll
                for (int i = 0; i < 4; i++) {
                    float4 v = p[i];
                    hw[2 * i]     = pack_f16x2(v.x, v.y);
                    hw[2 * i + 1] = pack_f16x2(v.z, v.w);
                }
            } else {
#pragma unroll
                for (int i = 0; i < 8; i++) hw[i] = 0u;
            }
            const uint32_t ab = sm + OFF_A + stage * 16384;
            sts128(ab + a_sts[0], hw[0], hw[1], hw[2], hw[3]);
            sts128(ab + a_sts[1], hw[4], hw[5], hw[6], hw[7]);
        }
        __syncthreads();

        const uint32_t Ahb = sm + OFF_A + stage * 16384;
        const uint32_t Whb = sm + OFF_W + (uint32_t)c * 16384;
#pragma unroll
        for (int ks = 0; ks < 4; ks++) {
            uint32_t ah[2][4];
#pragma unroll
            for (int am = 0; am < 2; am++)
                ldmx4(Ahb + aoff[am] + ((acolb + ks * 32) ^ axor[am]), ah[am]);
#pragma unroll
            for (int nb = 0; nb < 2; nb++) {
                uint32_t bh[4];
                ldmx4t(Whb + (uint32_t)ks * 4096 + brow + bcol[nb], bh);
#pragma unroll
                for (int am = 0; am < 2; am++) {
                    mma_f16(acc[am][nb * 2],     ah[am], bh[0], bh[1]);
                    mma_f16(acc[am][nb * 2 + 1], ah[am], bh[2], bh[3]);
                }
            }
        }
    }

    // ---- epilogue: direct fp16 STG + register/shuffle column stats ----
    const int colb = warp_n * 32 + (lane & 3) * 2;   // this thread's col base
    float2 b2[4];
#pragma unroll
    for (int na = 0; na < 4; na++)
        b2[na] = *(const float2*)&sbias[colb + na * 8];

    float s0[4], s1[4], q0[4], q1[4];
#pragma unroll
    for (int na = 0; na < 4; na++) { s0[na] = s1[na] = q0[na] = q1[na] = 0.f; }

#pragma unroll
    for (int am = 0; am < 2; am++) {
        const int rA = warp_m * 32 + am * 16 + (lane >> 2);
#pragma unroll
        for (int half = 0; half < 2; half++) {
            const int r = rA + half * 8;
            const bool v = (row0 + r) < U_NODES;
            __half* dst = g_h + (size_t)(row0 + r) * E_DIM + colb;
#pragma unroll
            for (int na = 0; na < 4; na++) {
                float x0 = acc[am][na][half * 2]     + b2[na].x;
                float x1 = acc[am][na][half * 2 + 1] + b2[na].y;
                if (v) {
                    *(uint32_t*)(dst + na * 8) = pack_f16x2(x0, x1);
                    s0[na] += x0; s1[na] += x1;
                    q0[na] += x0 * x0; q1[na] += x1 * x1;
                }
            }
        }
    }
#pragma unroll
    for (int m = 4; m <= 16; m <<= 1) {
#pragma unroll
        for (int na = 0; na < 4; na++) {
            s0[na] += __shfl_xor_sync(0xFFFFFFFFu, s0[na], m);
            s1[na] += __shfl_xor_sync(0xFFFFFFFFu, s1[na], m);
            q0[na] += __shfl_xor_sync(0xFFFFFFFFu, q0[na], m);
            q1[na] += __shfl_xor_sync(0xFFFFFFFFu, q1[na], m);
        }
    }
    __syncthreads();                       // MMA reads of A bufs done
    float* red_s = (float*)(smem + OFF_A);          // 4 x 128 floats
    float* red_q = red_s + 512;
    if (lane < 4) {
#pragma unroll
        for (int na = 0; na < 4; na++) {
            const int col = warp_n * 32 + na * 8 + lane * 2;
            red_s[warp_m * 128 + col]     = s0[na];
            red_s[warp_m * 128 + col + 1] = s1[na];
            red_q[warp_m * 128 + col]     = q0[na];
            red_q[warp_m * 128 + col + 1] = q1[na];
        }
    }
    __syncthreads();
    if (tid < 128) {
        float ts = red_s[tid] + red_s[128 + tid] +
                   red_s[256 + tid] + red_s[384 + tid];
        float tq = red_q[tid] + red_q[128 + tid] +
                   red_q[256 + tid] + red_q[384 + tid];
        g_part[blockIdx.x * 256 + tid]       = ts;
        g_part[blockIdx.x * 256 + 128 + tid] = tq;
    }
}

// ---------------------------------------------------------------------------
// Kernel 2: finalize BN stats (one block per embedding column)
// ---------------------------------------------------------------------------
__global__ void finalize_stats_kernel(const float* __restrict__ gamma,
                                      const float* __restrict__ beta)
{
    __shared__ float ss[256], sq[256];
    const int e = blockIdx.x;
    const int t = threadIdx.x;
    float s = 0.f, q = 0.f;
    for (int i = t; i < NTILES; i += 256) {
        s += g_part[i * 256 + e];
        q += g_part[i * 256 + 128 + e];
    }
    ss[t] = s; sq[t] = q;
    __syncthreads();
    for (int st = 128; st > 0; st >>= 1) {
        if (t < st) { ss[t] += ss[t + st]; sq[t] += sq[t + st]; }
        __syncthreads();
    }
    if (t == 0) {
        const float mu  = ss[0] * (1.0f / U_NODES);
        const float var = sq[0] * (1.0f / U_NODES) - mu * mu;
        const float a   = gamma[e] * rsqrtf(var + BN_EPS);
        g_ab[e]         = a;
        g_ab[E_DIM + e] = beta[e] - mu * a;
    }
}

// ---------------------------------------------------------------------------
// Kernel 3: out[b] = mean_k tanh(a * h[idx[b,k]] + c), h in fp16
// one warp per output row, uint2 (4 halves) per lane covers the 256B row
// ---------------------------------------------------------------------------
__global__ void __launch_bounds__(128)
gather_mean_kernel(const int* __restrict__ idx, float* __restrict__ out)
{
    __shared__ int sidx[4 * K_SAMP];
    const int b0 = blockIdx.x * 4;
    const int tid = threadIdx.x;
    const int w = tid >> 5;
    const int lane = tid & 31;
    for (int i = tid; i < 4 * K_SAMP; i += 128)
        sidx[i] = idx[b0 * K_SAMP + i];
    __syncthreads();

    const float4 a4 = *(const float4*)&g_ab[lane * 4];
    const float4 c4 = *(const float4*)&g_ab[E_DIM + lane * 4];
    float4 acc = make_float4(0.f, 0.f, 0.f, 0.f);
    const int* myidx = sidx + w * K_SAMP;
#pragma unroll 3
    for (int k = 0; k < K_SAMP; k++) {
        const uint2 u = __ldg((const uint2*)(g_h + (size_t)myidx[k] * E_DIM)
                              + lane);
        const float2 f0 = __half22float2(*(const half2*)&u.x);
        const float2 f1 = __half22float2(*(const half2*)&u.y);
        float t0, t1, t2, t3;
        asm("tanh.approx.f32 %0, %1;" : "=f"(t0) : "f"(fmaf(a4.x, f0.x, c4.x)));
        asm("tanh.approx.f32 %0, %1;" : "=f"(t1) : "f"(fmaf(a4.y, f0.y, c4.y)));
        asm("tanh.approx.f32 %0, %1;" : "=f"(t2) : "f"(fmaf(a4.z, f1.x, c4.z)));
        asm("tanh.approx.f32 %0, %1;" : "=f"(t3) : "f"(fmaf(a4.w, f1.y, c4.w)));
        acc.x += t0; acc.y += t1; acc.z += t2; acc.w += t3;
    }
    const float sc = 1.0f / K_SAMP;
    float4 o = make_float4(acc.x * sc, acc.y * sc, acc.z * sc, acc.w * sc);
    *(float4*)(out + (size_t)(b0 + w) * E_DIM + lane * 4) = o;
}

// ---------------------------------------------------------------------------
extern "C" void kernel_launch(void* const* d_in, const int* in_sizes, int n_in,
                              void* d_out, int out_size)
{
    const float* features = (const float*)d_in[0];
    const float* W        = (const float*)d_in[1];
    const float* bias     = (const float*)d_in[2];
    const float* gamma    = (const float*)d_in[3];
    const float* beta     = (const float*)d_in[4];
    const int*   sidx     = (const int*)d_in[5];
    float*       out      = (float*)d_out;

    cudaFuncSetAttribute(gemm_mma_kernel,
                         cudaFuncAttributeMaxDynamicSharedMemorySize, SMEM_TOTAL);

    prep_w_kernel<<<128, 256>>>(W);
    gemm_mma_kernel<<<NTILES, 512, SMEM_TOTAL>>>(features, bias);
    finalize_stats_kernel<<<128, 256>>>(gamma, beta);
    gather_mean_kernel<<<B_ROWS / 4, 128>>>(sidx, out);
}

// round 17
// speedup vs baseline: 1.6855x; 1.0039x over previous
#include <cuda_runtime.h>
#include <cuda_fp16.h>
#include <cstdint>

// ---------------------------------------------------------------------------
// Problem constants
// ---------------------------------------------------------------------------
#define U_NODES 200000
#define F_DIM   256
#define E_DIM   128
#define B_ROWS  20000
#define K_SAMP  33
#define BN_EPS  1e-5f

#define TM      128
#define KC      64                        // K chunk (fp16 elems)
#define NCH     (F_DIM / KC)              // 4
#define NTILES  ((U_NODES + TM - 1) / TM) // 1563

// SMEM layout (bytes, dynamic)
#define OFF_BIAS   0                          // 512 B
#define OFF_W      512                        // 64 KB (fp16 W, whole K)
#define OFF_A      (OFF_W + 65536)            // 2 stages x 16KB (fp16 A)
#define SMEM_TOTAL (OFF_A + 32768)            // 98816 -> 2 CTAs/SM

// ---------------------------------------------------------------------------
// Device scratch
// ---------------------------------------------------------------------------
__device__ __half g_h[(size_t)U_NODES * E_DIM];      // h in fp16 (51.2 MB)
__device__ float g_part[NTILES * 2 * E_DIM];
__device__ __align__(16) float g_ab[2 * E_DIM];
// W image: [K=256 rows][N=128] fp16 (256B rows), 16B-col XOR-swizzle by (k&7)
__device__ __align__(16) __half g_wh[F_DIM * E_DIM];

// ---------------------------------------------------------------------------
// Helpers
// ---------------------------------------------------------------------------
__device__ __forceinline__ uint32_t smem_u32(const void* p) {
    uint32_t a;
    asm("{ .reg .u64 t; cvta.to.shared.u64 t, %1; cvt.u32.u64 %0, t; }"
        : "=r"(a) : "l"(p));
    return a;
}
__device__ __forceinline__ void sts128(uint32_t addr, uint32_t a, uint32_t b,
                                       uint32_t c, uint32_t d) {
    asm volatile("st.shared.v4.b32 [%0], {%1, %2, %3, %4};"
                 :: "r"(addr), "r"(a), "r"(b), "r"(c), "r"(d) : "memory");
}
__device__ __forceinline__ void cp16(uint32_t s, const void* g) {
    asm volatile("cp.async.cg.shared.global [%0], [%1], 16;"
                 :: "r"(s), "l"(g) : "memory");
}
__device__ __forceinline__ void cp_commit() {
    asm volatile("cp.async.commit_group;" ::: "memory");
}
__device__ __forceinline__ void cp_wait0() {
    asm volatile("cp.async.wait_group 0;" ::: "memory");
}
__device__ __forceinline__ void ldmx4(uint32_t addr, uint32_t* r) {
    asm volatile("ldmatrix.sync.aligned.m8n8.x4.shared.b16 {%0,%1,%2,%3}, [%4];"
                 : "=r"(r[0]), "=r"(r[1]), "=r"(r[2]), "=r"(r[3]) : "r"(addr));
}
__device__ __forceinline__ void ldmx4t(uint32_t addr, uint32_t* r) {
    asm volatile("ldmatrix.sync.aligned.m8n8.x4.trans.shared.b16 {%0,%1,%2,%3}, [%4];"
                 : "=r"(r[0]), "=r"(r[1]), "=r"(r[2]), "=r"(r[3]) : "r"(addr));
}
__device__ __forceinline__ void mma_f16(float* d, const uint32_t* a,
                                        uint32_t b0, uint32_t b1) {
    asm volatile(
        "mma.sync.aligned.m16n8k16.row.col.f32.f16.f16.f32 "
        "{%0,%1,%2,%3}, {%4,%5,%6,%7}, {%8,%9}, {%0,%1,%2,%3};"
        : "+f"(d[0]), "+f"(d[1]), "+f"(d[2]), "+f"(d[3])
        : "r"(a[0]), "r"(a[1]), "r"(a[2]), "r"(a[3]), "r"(b0), "r"(b1));
}
__device__ __forceinline__ uint32_t pack_f16x2(float lo, float hi) {
    uint32_t r;
    asm("cvt.rn.f16x2.f32 %0, %1, %2;" : "=r"(r) : "f"(hi), "f"(lo));
    return r;
}

// ---------------------------------------------------------------------------
// Kernel 0: W [256,128] fp32 -> fp16, [K][N] row-major, swizzled.
// byte offset = k*256 + ((n*2) ^ ((k&7)<<4))
// ---------------------------------------------------------------------------
__global__ void prep_w_kernel(const float* __restrict__ W) {
    int idx = blockIdx.x * 256 + threadIdx.x;    // 0..32767
    int k = idx >> 7;
    int n = idx & 127;
    uint32_t off = (uint32_t)k * 256 + (((uint32_t)n * 2) ^ ((k & 7) << 4));
    g_wh[off >> 1] = __float2half_rn(W[idx]);
}

// ---------------------------------------------------------------------------
// Kernel 1: h = A @ W + b via mma.sync fp16, fused col stats, h stored fp16.
// 512 threads = 16 warps (4x4 grid of 32x32 tiles), 2 CTAs/SM.
// R9 structure; prologue reordered: chunk-0 production (LDG/convert/STS,
// W-independent) runs BEFORE cp.async wait, overlapping W's L2 transfer.
// ---------------------------------------------------------------------------
__global__ void __launch_bounds__(512, 2)
gemm_mma_kernel(const float* __restrict__ A, const float* __restrict__ bias)
{
    extern __shared__ char smem[];
    const uint32_t sm = smem_u32(smem);
    const int tid  = threadIdx.x;
    const int wid  = tid >> 5;
    const int lane = tid & 31;
    const int row0 = blockIdx.x * TM;
    const int warp_m = wid >> 2;          // 0..3 -> 32-row band
    const int warp_n = wid & 3;           // 0..3 -> 32-col band

    float* sbias = (float*)(smem + OFF_BIAS);
    if (tid < 128) sbias[tid] = bias[tid];

    // ---- issue full W load (64KB fp16) via cp.async (async; waited later) ----
    {
        const char* src = (const char*)g_wh;
        const uint32_t dst = sm + OFF_W;
#pragma unroll
        for (int j = 0; j < 8; j++) {
            const int u = tid + j * 512;          // 16B units, 0..4095
            cp16(dst + u * 16, src + (size_t)u * 16);
        }
        cp_commit();
    }

    // ---- producer mapping: thread -> (row, 16-float quarter) ----
    const int pr = tid >> 2;             // 0..127
    const int pq = tid & 3;
    const bool pvalid = (row0 + pr) < U_NODES;
    const float* aptr = A + (size_t)(row0 + pr) * F_DIM + pq * 16;
    uint32_t a_sts[2];
#pragma unroll
    for (int i = 0; i < 2; i++)
        a_sts[i] = (uint32_t)pr * 128 +
                   (((uint32_t)(pq * 32 + i * 16)) ^ ((pr & 7) << 4));

    // ---- chunk-0 production BEFORE W wait (overlaps W transfer) ----
    {
        uint32_t hw[8];
        if (pvalid) {
            const float4* p = (const float4*)(aptr);
#pragma unroll
            for (int i = 0; i < 4; i++) {
                float4 v = p[i];
                hw[2 * i]     = pack_f16x2(v.x, v.y);
                hw[2 * i + 1] = pack_f16x2(v.z, v.w);
            }
        } else {
#pragma unroll
            for (int i = 0; i < 8; i++) hw[i] = 0u;
        }
        const uint32_t ab = sm + OFF_A;            // stage 0
        sts128(ab + a_sts[0], hw[0], hw[1], hw[2], hw[3]);
        sts128(ab + a_sts[1], hw[4], hw[5], hw[6], hw[7]);
    }

    // ---- MMA-side addressing ----
    uint32_t aoff[2], axor[2];
#pragma unroll
    for (int am = 0; am < 2; am++) {
        int r = warp_m * 32 + am * 16 + (lane & 15);
        aoff[am] = (uint32_t)r * 128;
        axor[am] = (uint32_t)(r & 7) << 4;
    }
    const uint32_t acolb = (uint32_t)(lane >> 4) * 16;
    const int bk = lane & 15;
    uint32_t bcol[2];
#pragma unroll
    for (int nb = 0; nb < 2; nb++)
        bcol[nb] = (((uint32_t)(warp_n * 32 + nb * 16 + (lane >> 4) * 8) * 2)
                    ^ ((bk & 7) << 4));
    const uint32_t brow = (uint32_t)bk * 256;

    float acc[2][4][4];
#pragma unroll
    for (int am = 0; am < 2; am++)
#pragma unroll
        for (int na = 0; na < 4; na++)
#pragma unroll
            for (int q = 0; q < 4; q++) acc[am][na][q] = 0.f;

    cp_wait0();                           // W resident (overlapped above)
    __syncthreads();                      // chunk-0 STS + W visible to all

    for (int c = 0; c < NCH; c++) {
        const int stage = c & 1;

        // producer for chunk c (chunk 0 already staged in prologue)
        if (c > 0) {
            uint32_t hw[8];
            if (pvalid) {
                const float4* p = (const float4*)(aptr + c * KC);
#pragma unroll
                for (int i = 0; i < 4; i++) {
                    float4 v = p[i];
                    hw[2 * i]     = pack_f16x2(v.x, v.y);
                    hw[2 * i + 1] = pack_f16x2(v.z, v.w);
                }
            } else {
#pragma unroll
                for (int i = 0; i < 8; i++) hw[i] = 0u;
            }
            const uint32_t ab = sm + OFF_A + stage * 16384;
            sts128(ab + a_sts[0], hw[0], hw[1], hw[2], hw[3]);
            sts128(ab + a_sts[1], hw[4], hw[5], hw[6], hw[7]);
            __syncthreads();
        }

        const uint32_t Ahb = sm + OFF_A + stage * 16384;
        const uint32_t Whb = sm + OFF_W + (uint32_t)c * 16384;
#pragma unroll
        for (int ks = 0; ks < 4; ks++) {
            uint32_t ah[2][4];
#pragma unroll
            for (int am = 0; am < 2; am++)
                ldmx4(Ahb + aoff[am] + ((acolb + ks * 32) ^ axor[am]), ah[am]);
#pragma unroll
            for (int nb = 0; nb < 2; nb++) {
                uint32_t bh[4];
                ldmx4t(Whb + (uint32_t)ks * 4096 + brow + bcol[nb], bh);
#pragma unroll
                for (int am = 0; am < 2; am++) {
                    mma_f16(acc[am][nb * 2],     ah[am], bh[0], bh[1]);
                    mma_f16(acc[am][nb * 2 + 1], ah[am], bh[2], bh[3]);
                }
            }
        }
    }

    // ---- epilogue: direct fp16 STG + register/shuffle column stats ----
    const int colb = warp_n * 32 + (lane & 3) * 2;   // this thread's col base
    float2 b2[4];
#pragma unroll
    for (int na = 0; na < 4; na++)
        b2[na] = *(const float2*)&sbias[colb + na * 8];

    float s0[4], s1[4], q0[4], q1[4];
#pragma unroll
    for (int na = 0; na < 4; na++) { s0[na] = s1[na] = q0[na] = q1[na] = 0.f; }

#pragma unroll
    for (int am = 0; am < 2; am++) {
        const int rA = warp_m * 32 + am * 16 + (lane >> 2);
#pragma unroll
        for (int half = 0; half < 2; half++) {
            const int r = rA + half * 8;
            const bool v = (row0 + r) < U_NODES;
            __half* dst = g_h + (size_t)(row0 + r) * E_DIM + colb;
#pragma unroll
            for (int na = 0; na < 4; na++) {
                float x0 = acc[am][na][half * 2]     + b2[na].x;
                float x1 = acc[am][na][half * 2 + 1] + b2[na].y;
                if (v) {
                    *(uint32_t*)(dst + na * 8) = pack_f16x2(x0, x1);
                    s0[na] += x0; s1[na] += x1;
                    q0[na] += x0 * x0; q1[na] += x1 * x1;
                }
            }
        }
    }
#pragma unroll
    for (int m = 4; m <= 16; m <<= 1) {
#pragma unroll
        for (int na = 0; na < 4; na++) {
            s0[na] += __shfl_xor_sync(0xFFFFFFFFu, s0[na], m);
            s1[na] += __shfl_xor_sync(0xFFFFFFFFu, s1[na], m);
            q0[na] += __shfl_xor_sync(0xFFFFFFFFu, q0[na], m);
            q1[na] += __shfl_xor_sync(0xFFFFFFFFu, q1[na], m);
        }
    }
    __syncthreads();                       // MMA reads of A bufs done
    float* red_s = (float*)(smem + OFF_A);          // 4 x 128 floats
    float* red_q = red_s + 512;
    if (lane < 4) {
#pragma unroll
        for (int na = 0; na < 4; na++) {
            const int col = warp_n * 32 + na * 8 + lane * 2;
            red_s[warp_m * 128 + col]     = s0[na];
            red_s[warp_m * 128 + col + 1] = s1[na];
            red_q[warp_m * 128 + col]     = q0[na];
            red_q[warp_m * 128 + col + 1] = q1[na];
        }
    }
    __syncthreads();
    if (tid < 128) {
        float ts = red_s[tid] + red_s[128 + tid] +
                   red_s[256 + tid] + red_s[384 + tid];
        float tq = red_q[tid] + red_q[128 + tid] +
                   red_q[256 + tid] + red_q[384 + tid];
        g_part[blockIdx.x * 256 + tid]       = ts;
        g_part[blockIdx.x * 256 + 128 + tid] = tq;
    }
}

// ---------------------------------------------------------------------------
// Kernel 2: finalize BN stats (one block per embedding column)
// ---------------------------------------------------------------------------
__global__ void finalize_stats_kernel(const float* __restrict__ gamma,
                                      const float* __restrict__ beta)
{
    __shared__ float ss[256], sq[256];
    const int e = blockIdx.x;
    const int t = threadIdx.x;
    float s = 0.f, q = 0.f;
    for (int i = t; i < NTILES; i += 256) {
        s += g_part[i * 256 + e];
        q += g_part[i * 256 + 128 + e];
    }
    ss[t] = s; sq[t] = q;
    __syncthreads();
    for (int st = 128; st > 0; st >>= 1) {
        if (t < st) { ss[t] += ss[t + st]; sq[t] += sq[t + st]; }
        __syncthreads();
    }
    if (t == 0) {
        const float mu  = ss[0] * (1.0f / U_NODES);
        const float var = sq[0] * (1.0f / U_NODES) - mu * mu;
        const float a   = gamma[e] * rsqrtf(var + BN_EPS);
        g_ab[e]         = a;
        g_ab[E_DIM + e] = beta[e] - mu * a;
    }
}

// ---------------------------------------------------------------------------
// Kernel 3: out[b] = mean_k tanh(a * h[idx[b,k]] + c), h in fp16
// one warp per output row, uint2 (4 halves) per lane covers the 256B row
// ---------------------------------------------------------------------------
__global__ void __launch_bounds__(128)
gather_mean_kernel(const int* __restrict__ idx, float* __restrict__ out)
{
    __shared__ int sidx[4 * K_SAMP];
    const int b0 = blockIdx.x * 4;
    const int tid = threadIdx.x;
    const int w = tid >> 5;
    const int lane = tid & 31;
    for (int i = tid; i < 4 * K_SAMP; i += 128)
        sidx[i] = idx[b0 * K_SAMP + i];
    __syncthreads();

    const float4 a4 = *(const float4*)&g_ab[lane * 4];
    const float4 c4 = *(const float4*)&g_ab[E_DIM + lane * 4];
    float4 acc = make_float4(0.f, 0.f, 0.f, 0.f);
    const int* myidx = sidx + w * K_SAMP;
#pragma unroll 3
    for (int k = 0; k < K_SAMP; k++) {
        const uint2 u = __ldg((const uint2*)(g_h + (size_t)myidx[k] * E_DIM)
                              + lane);
        const float2 f0 = __half22float2(*(const half2*)&u.x);
        const float2 f1 = __half22float2(*(const half2*)&u.y);
        float t0, t1, t2, t3;
        asm("tanh.approx.f32 %0, %1;" : "=f"(t0) : "f"(fmaf(a4.x, f0.x, c4.x)));
        asm("tanh.approx.f32 %0, %1;" : "=f"(t1) : "f"(fmaf(a4.y, f0.y, c4.y)));
        asm("tanh.approx.f32 %0, %1;" : "=f"(t2) : "f"(fmaf(a4.z, f1.x, c4.z)));
        asm("tanh.approx.f32 %0, %1;" : "=f"(t3) : "f"(fmaf(a4.w, f1.y, c4.w)));
        acc.x += t0; acc.y += t1; acc.z += t2; acc.w += t3;
    }
    const float sc = 1.0f / K_SAMP;
    float4 o = make_float4(acc.x * sc, acc.y * sc, acc.z * sc, acc.w * sc);
    *(float4*)(out + (size_t)(b0 + w) * E_DIM + lane * 4) = o;
}

// ---------------------------------------------------------------------------
extern "C" void kernel_launch(void* const* d_in, const int* in_sizes, int n_in,
                              void* d_out, int out_size)
{
    const float* features = (const float*)d_in[0];
    const float* W        = (const float*)d_in[1];
    const float* bias     = (const float*)d_in[2];
    const float* gamma    = (const float*)d_in[3];
    const float* beta     = (const float*)d_in[4];
    const int*   sidx     = (const int*)d_in[5];
    float*       out      = (float*)d_out;

    cudaFuncSetAttribute(gemm_mma_kernel,
                         cudaFuncAttributeMaxDynamicSharedMemorySize, SMEM_TOTAL);

    prep_w_kernel<<<128, 256>>>(W);
    gemm_mma_kernel<<<NTILES, 512, SMEM_TOTAL>>>(features, bias);
    finalize_stats_kernel<<<128, 256>>>(gamma, beta);
    gather_mean_kernel<<<B_ROWS / 4, 128>>>(sidx, out);
}